// round 5
// baseline (speedup 1.0000x reference)
#include <cuda_runtime.h>
#include <cuda_bf16.h>

#define NN   4096
#define FIN  256
#define C1   512     // H1 * HID
#define H1   8
#define HID  64
#define OUT2 128
#define MAXN 512
#define WPAD (MAXN + 4)

// ---------------- scratch (no allocations allowed) ----------------
__device__ float g_h1[NN * C1];          // layer-1 features fp32 (for scores)
__device__ uint4 g_h1b[NN * C1 / 8];     // layer-1 features bf16 (for gather)
__device__ float g_hmid[NN * C1];        // layer-1 output fp32
__device__ float g_h2[NN * OUT2];        // layer-2 features fp32 (for scores)
__device__ uint4 g_h2b[NN * OUT2 / 8];   // layer-2 features bf16 (for gather)
__device__ float g_asrc1[NN * H1];
__device__ float g_adst1[NN * H1];
__device__ float g_asrc2[NN];
__device__ float g_adst2[NN];
__device__ unsigned short g_nbr[NN * MAXN];
__device__ int g_cnt[NN];

// packed f32x2 FMA: acc(pair) += unpack_bf16x2(u) * wv(pair)
#define FF2(accp, u, wv)                                                     \
    asm("{\n\t"                                                              \
        ".reg .b32 lo, hi;\n\t"                                              \
        ".reg .b64 v;\n\t"                                                   \
        "shl.b32 lo, %1, 16;\n\t"                                            \
        "and.b32 hi, %1, 0xffff0000;\n\t"                                    \
        "mov.b64 v, {lo, hi};\n\t"                                           \
        "fma.rn.f32x2 %0, v, %2, %0;\n\t"                                    \
        "}" : "+l"(accp) : "r"(u), "l"(wv))

// ---------------- CSR build (deterministic, ordered) ----------------
__global__ void build_csr(const float* __restrict__ adj) {
    int row = blockIdx.x;
    int t   = threadIdx.x;                 // 256
    const float* arow = adj + (size_t)row * NN;
    int base = t * 16;

    float av[16];
    #pragma unroll
    for (int q = 0; q < 4; q++) {
        float4 v = *(const float4*)(arow + base + q * 4);
        av[q * 4 + 0] = v.x; av[q * 4 + 1] = v.y;
        av[q * 4 + 2] = v.z; av[q * 4 + 3] = v.w;
    }
    int cnt = 0;
    #pragma unroll
    for (int k = 0; k < 16; k++) cnt += (av[k] != 0.0f);

    __shared__ int s[256];
    s[t] = cnt;
    __syncthreads();
    for (int off = 1; off < 256; off <<= 1) {
        int v = (t >= off) ? s[t - off] : 0;
        __syncthreads();
        s[t] += v;
        __syncthreads();
    }
    int pos = s[t] - cnt;
    unsigned short* out = g_nbr + (size_t)row * MAXN;
    #pragma unroll
    for (int k = 0; k < 16; k++) {
        if (av[k] != 0.0f) {
            if (pos < MAXN) out[pos] = (unsigned short)(base + k);
            pos++;
        }
    }
    if (t == 255) g_cnt[row] = (s[255] < MAXN) ? s[255] : MAXN;
}

// ------ tiled fp32 GEMM: C = A[MxK]*B[KxN]; optional bf16 secondary output ------
template <int BM, int BN, int BK, int TM, int TN>
__global__ void sgemm(const float* __restrict__ A, const float* __restrict__ B,
                      float* __restrict__ C, __nv_bfloat162* __restrict__ Cb,
                      int M, int N, int K) {
    __shared__ float As[BK][BM];
    __shared__ float Bs[BK][BN];
    const int THREADS = (BM / TM) * (BN / TN);   // 256
    int tid = threadIdx.x;
    int tx  = tid % (BN / TN);
    int ty  = tid / (BN / TN);
    int m0  = blockIdx.y * BM;
    int n0  = blockIdx.x * BN;

    float acc[TM][TN];
    #pragma unroll
    for (int i = 0; i < TM; i++)
        #pragma unroll
        for (int j = 0; j < TN; j++) acc[i][j] = 0.0f;

    const int A4 = BM * BK / 4;
    const int B4 = BK * BN / 4;

    for (int k0 = 0; k0 < K; k0 += BK) {
        #pragma unroll
        for (int e = tid; e < A4; e += THREADS) {
            int m  = e / (BK / 4);
            int k4 = e % (BK / 4);
            float4 v = *(const float4*)&A[(size_t)(m0 + m) * K + k0 + k4 * 4];
            As[k4 * 4 + 0][m] = v.x;
            As[k4 * 4 + 1][m] = v.y;
            As[k4 * 4 + 2][m] = v.z;
            As[k4 * 4 + 3][m] = v.w;
        }
        #pragma unroll
        for (int e = tid; e < B4; e += THREADS) {
            int k  = e / (BN / 4);
            int n4 = e % (BN / 4);
            *(float4*)&Bs[k][n4 * 4] =
                *(const float4*)&B[(size_t)(k0 + k) * N + n0 + n4 * 4];
        }
        __syncthreads();
        #pragma unroll
        for (int kk = 0; kk < BK; kk++) {
            float a[TM], b[TN];
            #pragma unroll
            for (int i = 0; i < TM; i++) a[i] = As[kk][ty * TM + i];
            #pragma unroll
            for (int j = 0; j < TN; j++) b[j] = Bs[kk][tx * TN + j];
            #pragma unroll
            for (int i = 0; i < TM; i++)
                #pragma unroll
                for (int j = 0; j < TN; j++) acc[i][j] += a[i] * b[j];
        }
        __syncthreads();
    }
    #pragma unroll
    for (int i = 0; i < TM; i++) {
        size_t roff = (size_t)(m0 + ty * TM + i) * N + n0 + tx * TN;
        #pragma unroll
        for (int j4 = 0; j4 < TN / 4; j4++) {
            float4 v = make_float4(acc[i][j4 * 4 + 0], acc[i][j4 * 4 + 1],
                                   acc[i][j4 * 4 + 2], acc[i][j4 * 4 + 3]);
            *(float4*)&C[roff + j4 * 4] = v;
        }
        if (Cb) {
            #pragma unroll
            for (int j2 = 0; j2 < TN / 2; j2++)
                Cb[(roff >> 1) + j2] =
                    __floats2bfloat162_rn(acc[i][j2 * 2], acc[i][j2 * 2 + 1]);
        }
    }
}

// ---------------- attention scores, layer 1 ----------------
__global__ void scores1(const float* __restrict__ att_src,
                        const float* __restrict__ att_dst) {
    int n = blockIdx.x;
    int c = threadIdx.x;                  // 512
    __shared__ float ps[C1], pd[C1];
    float hv = g_h1[(size_t)n * C1 + c];
    ps[c] = hv * att_src[c];
    pd[c] = hv * att_dst[c];
    __syncthreads();
    for (int off = 32; off >= 1; off >>= 1) {
        if ((c & 63) < off) { ps[c] += ps[c + off]; pd[c] += pd[c + off]; }
        __syncthreads();
    }
    if ((c & 63) == 0) {
        g_asrc1[n * H1 + (c >> 6)] = ps[c];
        g_adst1[n * H1 + (c >> 6)] = pd[c];
    }
}

// ---------------- attention scores, layer 2 ----------------
__global__ void scores2(const float* __restrict__ att_src,
                        const float* __restrict__ att_dst) {
    int n = blockIdx.x;
    int c = threadIdx.x;                  // 128
    __shared__ float ps[OUT2], pd[OUT2];
    float hv = g_h2[(size_t)n * OUT2 + c];
    ps[c] = hv * att_src[c];
    pd[c] = hv * att_dst[c];
    __syncthreads();
    for (int off = 64; off >= 1; off >>= 1) {
        if (c < off) { ps[c] += ps[c + off]; pd[c] += pd[c + off]; }
        __syncthreads();
    }
    if (c == 0) { g_asrc2[n] = ps[0]; g_adst2[n] = pd[0]; }
}

// ---------------- layer-1 sparse aggregation (bf16 + f32x2 FMA) ----------------
__global__ void __launch_bounds__(512) agg1(const float* __restrict__ b1) {
    int i = blockIdx.x;
    int t = threadIdx.x;                  // 512
    __shared__ unsigned short s_nbr[MAXN];
    __shared__ float s_w[H1][WPAD];
    __shared__ float s_part[H1 * 64];
    __shared__ float s_den[H1];
    __shared__ float s_red[16][C1];       // [group][channel] 32KB

    int cnt = g_cnt[i];
    for (int jj = t; jj < cnt; jj += 512) s_nbr[jj] = g_nbr[(size_t)i * MAXN + jj];
    __syncthreads();

    // phase 1: edge weights
    float adst[H1];
    {
        float4 d0 = *(const float4*)&g_adst1[i * H1];
        float4 d1 = *(const float4*)&g_adst1[i * H1 + 4];
        adst[0] = d0.x; adst[1] = d0.y; adst[2] = d0.z; adst[3] = d0.w;
        adst[4] = d1.x; adst[5] = d1.y; adst[6] = d1.z; adst[7] = d1.w;
    }
    for (int jj = t; jj < cnt; jj += 512) {
        int j = s_nbr[jj];
        float4 a0 = *(const float4*)&g_asrc1[j * H1];
        float4 a1 = *(const float4*)&g_asrc1[j * H1 + 4];
        float av[H1] = {a0.x, a0.y, a0.z, a0.w, a1.x, a1.y, a1.z, a1.w};
        #pragma unroll
        for (int h = 0; h < H1; h++) {
            float v = av[h] + adst[h];
            v = v > 0.0f ? v : 0.2f * v;
            s_w[h][jj] = __expf(v);
        }
    }
    __syncthreads();

    // denominator per head
    {
        int h = t >> 6, k = t & 63;
        float s = 0.0f;
        for (int jj = k; jj < cnt; jj += 64) s += s_w[h][jj];
        s_part[t] = s;
        __syncthreads();
        for (int off = 32; off >= 1; off >>= 1) {
            if (k < off) s_part[t] += s_part[t + off];
            __syncthreads();
        }
        if (k == 0) s_den[h] = s_part[t];
        __syncthreads();
    }

    // phase 2: lane c16 covers channels [c16*16, c16*16+16); 16 edge groups
    {
        int c16 = t & 31;                 // 32 lanes
        int g   = t >> 5;                 // 0..15
        int h   = c16 >> 2;               // head for this 16-channel span
        const float* wrow = s_w[h];
        unsigned long long acc[8];
        #pragma unroll
        for (int k = 0; k < 8; k++) acc[k] = 0ULL;

        const uint4* hb = g_h1b;
        for (int jj = g; jj < cnt; jj += 16) {
            int j = s_nbr[jj];
            const uint4* p = hb + (size_t)j * (C1 / 8) + c16 * 2;
            uint4 v0 = p[0];
            uint4 v1 = p[1];
            float w = wrow[jj];
            unsigned long long wv;
            asm("mov.b64 %0, {%1, %1};" : "=l"(wv) : "f"(w));
            FF2(acc[0], v0.x, wv); FF2(acc[1], v0.y, wv);
            FF2(acc[2], v0.z, wv); FF2(acc[3], v0.w, wv);
            FF2(acc[4], v1.x, wv); FF2(acc[5], v1.y, wv);
            FF2(acc[6], v1.z, wv); FF2(acc[7], v1.w, wv);
        }
        #pragma unroll
        for (int k = 0; k < 8; k++) {
            unsigned lo, hi;
            asm("mov.b64 {%0, %1}, %2;" : "=r"(lo), "=r"(hi) : "l"(acc[k]));
            s_red[g][c16 * 16 + 2 * k]     = __uint_as_float(lo);
            s_red[g][c16 * 16 + 2 * k + 1] = __uint_as_float(hi);
        }
        __syncthreads();

        // final: channel c = t, sum over 16 groups
        float s = 0.0f;
        #pragma unroll
        for (int gg = 0; gg < 16; gg++) s += s_red[gg][t];
        float v = s / s_den[t >> 6] + b1[t];
        v = v > 0.0f ? v : 0.01f * v;
        g_hmid[(size_t)i * C1 + t] = v;
    }
}

// ---------------- layer-2 sparse aggregation (bf16 + f32x2 FMA) ----------------
__global__ void __launch_bounds__(128) agg2(const float* __restrict__ b2,
                                            float* __restrict__ out) {
    int i = blockIdx.x;
    int t = threadIdx.x;                  // 128
    __shared__ unsigned short s_nbr[MAXN];
    __shared__ float s_w[MAXN];
    __shared__ float s_part[OUT2];
    __shared__ float s_den;
    __shared__ float s_red[16][OUT2];     // 8KB

    int cnt = g_cnt[i];
    for (int jj = t; jj < cnt; jj += 128) s_nbr[jj] = g_nbr[(size_t)i * MAXN + jj];
    __syncthreads();

    float adst = g_adst2[i];
    for (int jj = t; jj < cnt; jj += 128) {
        float v = g_asrc2[s_nbr[jj]] + adst;
        v = v > 0.0f ? v : 0.2f * v;
        s_w[jj] = __expf(v);
    }
    __syncthreads();

    float s = 0.0f;
    for (int jj = t; jj < cnt; jj += 128) s += s_w[jj];
    s_part[t] = s;
    __syncthreads();
    for (int off = 64; off >= 1; off >>= 1) {
        if (t < off) s_part[t] += s_part[t + off];
        __syncthreads();
    }
    if (t == 0) s_den = s_part[0];
    __syncthreads();

    // lane c16 covers channels [c16*16, c16*16+16); 16 edge groups
    {
        int c16 = t & 7;                  // 8 lanes
        int g   = t >> 3;                 // 0..15
        unsigned long long acc[8];
        #pragma unroll
        for (int k = 0; k < 8; k++) acc[k] = 0ULL;

        const uint4* hb = g_h2b;
        for (int jj = g; jj < cnt; jj += 16) {
            int j = s_nbr[jj];
            const uint4* p = hb + (size_t)j * (OUT2 / 8) + c16 * 2;
            uint4 v0 = p[0];
            uint4 v1 = p[1];
            float w = s_w[jj];
            unsigned long long wv;
            asm("mov.b64 %0, {%1, %1};" : "=l"(wv) : "f"(w));
            FF2(acc[0], v0.x, wv); FF2(acc[1], v0.y, wv);
            FF2(acc[2], v0.z, wv); FF2(acc[3], v0.w, wv);
            FF2(acc[4], v1.x, wv); FF2(acc[5], v1.y, wv);
            FF2(acc[6], v1.z, wv); FF2(acc[7], v1.w, wv);
        }
        #pragma unroll
        for (int k = 0; k < 8; k++) {
            unsigned lo, hi;
            asm("mov.b64 {%0, %1}, %2;" : "=r"(lo), "=r"(hi) : "l"(acc[k]));
            s_red[g][c16 * 16 + 2 * k]     = __uint_as_float(lo);
            s_red[g][c16 * 16 + 2 * k + 1] = __uint_as_float(hi);
        }
        __syncthreads();

        float ss = 0.0f;
        #pragma unroll
        for (int gg = 0; gg < 16; gg++) ss += s_red[gg][t];
        float v = ss / s_den + b2[t];
        v = v > 0.0f ? v : 0.01f * v;
        out[(size_t)i * OUT2 + t] = v;
    }
}

// ---------------- launch ----------------
extern "C" void kernel_launch(void* const* d_in, const int* in_sizes, int n_in,
                              void* d_out, int out_size) {
    const float* x   = (const float*)d_in[0];
    const float* adj = (const float*)d_in[1];
    const float* w1  = (const float*)d_in[2];
    const float* as1 = (const float*)d_in[3];
    const float* ad1 = (const float*)d_in[4];
    const float* b1  = (const float*)d_in[5];
    const float* w2  = (const float*)d_in[6];
    const float* as2 = (const float*)d_in[7];
    const float* ad2 = (const float*)d_in[8];
    const float* b2  = (const float*)d_in[9];
    float* out = (float*)d_out;

    float *h1p, *hmidp, *h2p;
    __nv_bfloat162 *h1bp, *h2bp;
    cudaGetSymbolAddress((void**)&h1p,   g_h1);
    cudaGetSymbolAddress((void**)&hmidp, g_hmid);
    cudaGetSymbolAddress((void**)&h2p,   g_h2);
    cudaGetSymbolAddress((void**)&h1bp,  g_h1b);
    cudaGetSymbolAddress((void**)&h2bp,  g_h2b);

    build_csr<<<NN, 256>>>(adj);

    // h1 = x @ w1 : [4096,256] x [256,512]  (+ bf16 copy)
    sgemm<128, 128, 8, 8, 8><<<dim3(C1 / 128, NN / 128), 256>>>(
        x, w1, h1p, h1bp, NN, C1, FIN);

    scores1<<<NN, C1>>>(as1, ad1);
    agg1<<<NN, C1>>>(b1);

    // h2 = hmid @ w2 : [4096,512] x [512,128]  (+ bf16 copy)
    sgemm<64, 64, 16, 4, 4><<<dim3(OUT2 / 64, NN / 64), 256>>>(
        hmidp, w2, h2p, h2bp, NN, OUT2, C1);

    scores2<<<NN, OUT2>>>(as2, ad2);
    agg2<<<NN, OUT2>>>(b2, out);
}

// round 8
// speedup vs baseline: 1.6951x; 1.6951x over previous
#include <cuda_runtime.h>
#include <cuda_bf16.h>

#define NN   4096
#define FIN  256
#define C1   512     // H1 * HID
#define H1   8
#define HID  64
#define OUT2 128
#define MAXN 512
#define WPAD (MAXN + 4)

// ---------------- scratch (no allocations allowed) ----------------
__device__ float g_h1[NN * C1];          // layer-1 features fp32 (for scores)
__device__ uint4 g_h1b[NN * C1 / 8];     // layer-1 features bf16 (for gather)
__device__ float g_hmid[NN * C1];        // layer-1 output fp32
__device__ float g_h2[NN * OUT2];        // layer-2 features fp32 (for scores)
__device__ uint4 g_h2b[NN * OUT2 / 8];   // layer-2 features bf16 (for gather)
__device__ float g_asrc1[NN * H1];
__device__ float g_adst1[NN * H1];
__device__ float g_asrc2[NN];
__device__ float g_adst2[NN];
__device__ unsigned short g_nbr[NN * MAXN];
__device__ int g_cnt[NN];

__device__ __forceinline__ float bflo(unsigned u) { return __uint_as_float(u << 16); }
__device__ __forceinline__ float bfhi(unsigned u) { return __uint_as_float(u & 0xffff0000u); }

// ---------------- CSR build (deterministic, ordered) ----------------
__global__ void build_csr(const float* __restrict__ adj) {
    int row = blockIdx.x;
    int t   = threadIdx.x;                 // 256
    const float* arow = adj + (size_t)row * NN;
    int base = t * 16;

    float av[16];
    #pragma unroll
    for (int q = 0; q < 4; q++) {
        float4 v = *(const float4*)(arow + base + q * 4);
        av[q * 4 + 0] = v.x; av[q * 4 + 1] = v.y;
        av[q * 4 + 2] = v.z; av[q * 4 + 3] = v.w;
    }
    int cnt = 0;
    #pragma unroll
    for (int k = 0; k < 16; k++) cnt += (av[k] != 0.0f);

    __shared__ int s[256];
    s[t] = cnt;
    __syncthreads();
    for (int off = 1; off < 256; off <<= 1) {
        int v = (t >= off) ? s[t - off] : 0;
        __syncthreads();
        s[t] += v;
        __syncthreads();
    }
    int pos = s[t] - cnt;
    unsigned short* out = g_nbr + (size_t)row * MAXN;
    #pragma unroll
    for (int k = 0; k < 16; k++) {
        if (av[k] != 0.0f) {
            if (pos < MAXN) out[pos] = (unsigned short)(base + k);
            pos++;
        }
    }
    if (t == 255) g_cnt[row] = (s[255] < MAXN) ? s[255] : MAXN;
}

// ------ tiled fp32 GEMM: C = A[MxK]*B[KxN]; optional bf16 secondary output ------
template <int BM, int BN, int BK, int TM, int TN>
__global__ void sgemm(const float* __restrict__ A, const float* __restrict__ B,
                      float* __restrict__ C, __nv_bfloat162* __restrict__ Cb,
                      int M, int N, int K) {
    __shared__ float As[BK][BM];
    __shared__ float Bs[BK][BN];
    const int THREADS = (BM / TM) * (BN / TN);   // 256
    int tid = threadIdx.x;
    int tx  = tid % (BN / TN);
    int ty  = tid / (BN / TN);
    int m0  = blockIdx.y * BM;
    int n0  = blockIdx.x * BN;

    float acc[TM][TN];
    #pragma unroll
    for (int i = 0; i < TM; i++)
        #pragma unroll
        for (int j = 0; j < TN; j++) acc[i][j] = 0.0f;

    const int A4 = BM * BK / 4;
    const int B4 = BK * BN / 4;

    for (int k0 = 0; k0 < K; k0 += BK) {
        #pragma unroll
        for (int e = tid; e < A4; e += THREADS) {
            int m  = e / (BK / 4);
            int k4 = e % (BK / 4);
            float4 v = *(const float4*)&A[(size_t)(m0 + m) * K + k0 + k4 * 4];
            As[k4 * 4 + 0][m] = v.x;
            As[k4 * 4 + 1][m] = v.y;
            As[k4 * 4 + 2][m] = v.z;
            As[k4 * 4 + 3][m] = v.w;
        }
        #pragma unroll
        for (int e = tid; e < B4; e += THREADS) {
            int k  = e / (BN / 4);
            int n4 = e % (BN / 4);
            *(float4*)&Bs[k][n4 * 4] =
                *(const float4*)&B[(size_t)(k0 + k) * N + n0 + n4 * 4];
        }
        __syncthreads();
        #pragma unroll
        for (int kk = 0; kk < BK; kk++) {
            float a[TM], b[TN];
            #pragma unroll
            for (int i = 0; i < TM; i++) a[i] = As[kk][ty * TM + i];
            #pragma unroll
            for (int j = 0; j < TN; j++) b[j] = Bs[kk][tx * TN + j];
            #pragma unroll
            for (int i = 0; i < TM; i++)
                #pragma unroll
                for (int j = 0; j < TN; j++) acc[i][j] += a[i] * b[j];
        }
        __syncthreads();
    }
    #pragma unroll
    for (int i = 0; i < TM; i++) {
        size_t roff = (size_t)(m0 + ty * TM + i) * N + n0 + tx * TN;
        #pragma unroll
        for (int j4 = 0; j4 < TN / 4; j4++) {
            float4 v = make_float4(acc[i][j4 * 4 + 0], acc[i][j4 * 4 + 1],
                                   acc[i][j4 * 4 + 2], acc[i][j4 * 4 + 3]);
            *(float4*)&C[roff + j4 * 4] = v;
        }
        if (Cb) {
            #pragma unroll
            for (int j2 = 0; j2 < TN / 2; j2++)
                Cb[(roff >> 1) + j2] =
                    __floats2bfloat162_rn(acc[i][j2 * 2], acc[i][j2 * 2 + 1]);
        }
    }
}

// ---------------- attention scores, layer 1 ----------------
__global__ void scores1(const float* __restrict__ att_src,
                        const float* __restrict__ att_dst) {
    int n = blockIdx.x;
    int c = threadIdx.x;                  // 512
    __shared__ float ps[C1], pd[C1];
    float hv = g_h1[(size_t)n * C1 + c];
    ps[c] = hv * att_src[c];
    pd[c] = hv * att_dst[c];
    __syncthreads();
    for (int off = 32; off >= 1; off >>= 1) {
        if ((c & 63) < off) { ps[c] += ps[c + off]; pd[c] += pd[c + off]; }
        __syncthreads();
    }
    if ((c & 63) == 0) {
        g_asrc1[n * H1 + (c >> 6)] = ps[c];
        g_adst1[n * H1 + (c >> 6)] = pd[c];
    }
}

// ---------------- attention scores, layer 2 ----------------
__global__ void scores2(const float* __restrict__ att_src,
                        const float* __restrict__ att_dst) {
    int n = blockIdx.x;
    int c = threadIdx.x;                  // 128
    __shared__ float ps[OUT2], pd[OUT2];
    float hv = g_h2[(size_t)n * OUT2 + c];
    ps[c] = hv * att_src[c];
    pd[c] = hv * att_dst[c];
    __syncthreads();
    for (int off = 64; off >= 1; off >>= 1) {
        if (c < off) { ps[c] += ps[c + off]; pd[c] += pd[c + off]; }
        __syncthreads();
    }
    if (c == 0) { g_asrc2[n] = ps[0]; g_adst2[n] = pd[0]; }
}

// ---------------- layer-1 sparse aggregation (bf16 uint4 gather, MLP=2) ----------------
__global__ void __launch_bounds__(512) agg1(const float* __restrict__ b1) {
    int i = blockIdx.x;
    int t = threadIdx.x;                  // 512
    __shared__ unsigned short s_nbr[MAXN];
    __shared__ float s_w[H1][WPAD];
    __shared__ float s_part[H1 * 64];
    __shared__ float s_den[H1];
    __shared__ float s_red[8][8][64];     // [group][k][c8] 16KB

    int cnt = g_cnt[i];
    for (int jj = t; jj < cnt; jj += 512) s_nbr[jj] = g_nbr[(size_t)i * MAXN + jj];
    __syncthreads();

    // phase 1: edge weights
    float adst[H1];
    {
        float4 d0 = *(const float4*)&g_adst1[i * H1];
        float4 d1 = *(const float4*)&g_adst1[i * H1 + 4];
        adst[0] = d0.x; adst[1] = d0.y; adst[2] = d0.z; adst[3] = d0.w;
        adst[4] = d1.x; adst[5] = d1.y; adst[6] = d1.z; adst[7] = d1.w;
    }
    for (int jj = t; jj < cnt; jj += 512) {
        int j = s_nbr[jj];
        float4 a0 = *(const float4*)&g_asrc1[j * H1];
        float4 a1 = *(const float4*)&g_asrc1[j * H1 + 4];
        float av[H1] = {a0.x, a0.y, a0.z, a0.w, a1.x, a1.y, a1.z, a1.w};
        #pragma unroll
        for (int h = 0; h < H1; h++) {
            float v = av[h] + adst[h];
            v = v > 0.0f ? v : 0.2f * v;
            s_w[h][jj] = __expf(v);
        }
    }
    __syncthreads();

    // denominator per head
    {
        int h = t >> 6, k = t & 63;
        float s = 0.0f;
        for (int jj = k; jj < cnt; jj += 64) s += s_w[h][jj];
        s_part[t] = s;
        __syncthreads();
        for (int off = 32; off >= 1; off >>= 1) {
            if (k < off) s_part[t] += s_part[t + off];
            __syncthreads();
        }
        if (k == 0) s_den[h] = s_part[t];
        __syncthreads();
    }

    // phase 2: bf16 gather, 2-edge unroll (two independent acc sets)
    {
        int c8 = t & 63;
        int g  = t >> 6;                  // 0..7
        int h  = c8 >> 3;
        const float* wrow = s_w[h];
        const uint4* hb = g_h1b;
        float accA[8] = {0, 0, 0, 0, 0, 0, 0, 0};
        float accB[8] = {0, 0, 0, 0, 0, 0, 0, 0};

        int jj = g;
        for (; jj + 8 < cnt; jj += 16) {
            int j0 = s_nbr[jj];
            int j1 = s_nbr[jj + 8];
            uint4 v0 = hb[(size_t)j0 * (C1 / 8) + c8];
            uint4 v1 = hb[(size_t)j1 * (C1 / 8) + c8];
            float w0 = wrow[jj];
            float w1 = wrow[jj + 8];
            accA[0] += w0 * bflo(v0.x); accA[1] += w0 * bfhi(v0.x);
            accA[2] += w0 * bflo(v0.y); accA[3] += w0 * bfhi(v0.y);
            accA[4] += w0 * bflo(v0.z); accA[5] += w0 * bfhi(v0.z);
            accA[6] += w0 * bflo(v0.w); accA[7] += w0 * bfhi(v0.w);
            accB[0] += w1 * bflo(v1.x); accB[1] += w1 * bfhi(v1.x);
            accB[2] += w1 * bflo(v1.y); accB[3] += w1 * bfhi(v1.y);
            accB[4] += w1 * bflo(v1.z); accB[5] += w1 * bfhi(v1.z);
            accB[6] += w1 * bflo(v1.w); accB[7] += w1 * bfhi(v1.w);
        }
        if (jj < cnt) {
            int j0 = s_nbr[jj];
            uint4 v0 = hb[(size_t)j0 * (C1 / 8) + c8];
            float w0 = wrow[jj];
            accA[0] += w0 * bflo(v0.x); accA[1] += w0 * bfhi(v0.x);
            accA[2] += w0 * bflo(v0.y); accA[3] += w0 * bfhi(v0.y);
            accA[4] += w0 * bflo(v0.z); accA[5] += w0 * bfhi(v0.z);
            accA[6] += w0 * bflo(v0.w); accA[7] += w0 * bfhi(v0.w);
        }
        #pragma unroll
        for (int k = 0; k < 8; k++) s_red[g][k][c8] = accA[k] + accB[k];
        __syncthreads();

        if (t < 64) {
            float inv = 1.0f / s_den[t >> 3];
            float o[8];
            #pragma unroll
            for (int k = 0; k < 8; k++) {
                float s = 0.0f;
                #pragma unroll
                for (int gg = 0; gg < 8; gg++) s += s_red[gg][k][t];
                float v = s * inv + b1[t * 8 + k];
                o[k] = v > 0.0f ? v : 0.01f * v;
            }
            float4* dst = (float4*)&g_hmid[(size_t)i * C1 + t * 8];
            dst[0] = make_float4(o[0], o[1], o[2], o[3]);
            dst[1] = make_float4(o[4], o[5], o[6], o[7]);
        }
    }
}

// ---------------- layer-2 sparse aggregation (bf16 uint4 gather, MLP=2) ----------------
__global__ void __launch_bounds__(128) agg2(const float* __restrict__ b2,
                                            float* __restrict__ out) {
    int i = blockIdx.x;
    int t = threadIdx.x;                  // 128
    __shared__ unsigned short s_nbr[MAXN];
    __shared__ float s_w[MAXN];
    __shared__ float s_part[OUT2];
    __shared__ float s_den;
    __shared__ float s_red[8][8][16];     // 4KB

    int cnt = g_cnt[i];
    for (int jj = t; jj < cnt; jj += 128) s_nbr[jj] = g_nbr[(size_t)i * MAXN + jj];
    __syncthreads();

    float adst = g_adst2[i];
    for (int jj = t; jj < cnt; jj += 128) {
        float v = g_asrc2[s_nbr[jj]] + adst;
        v = v > 0.0f ? v : 0.2f * v;
        s_w[jj] = __expf(v);
    }
    __syncthreads();

    float s = 0.0f;
    for (int jj = t; jj < cnt; jj += 128) s += s_w[jj];
    s_part[t] = s;
    __syncthreads();
    for (int off = 64; off >= 1; off >>= 1) {
        if (t < off) s_part[t] += s_part[t + off];
        __syncthreads();
    }
    if (t == 0) s_den = s_part[0];
    __syncthreads();

    // bf16 gather, 2-edge unroll
    {
        int c8 = t & 15;
        int g  = t >> 4;                  // 0..7
        const uint4* hb = g_h2b;
        float accA[8] = {0, 0, 0, 0, 0, 0, 0, 0};
        float accB[8] = {0, 0, 0, 0, 0, 0, 0, 0};

        int jj = g;
        for (; jj + 8 < cnt; jj += 16) {
            int j0 = s_nbr[jj];
            int j1 = s_nbr[jj + 8];
            uint4 v0 = hb[(size_t)j0 * (OUT2 / 8) + c8];
            uint4 v1 = hb[(size_t)j1 * (OUT2 / 8) + c8];
            float w0 = s_w[jj];
            float w1 = s_w[jj + 8];
            accA[0] += w0 * bflo(v0.x); accA[1] += w0 * bfhi(v0.x);
            accA[2] += w0 * bflo(v0.y); accA[3] += w0 * bfhi(v0.y);
            accA[4] += w0 * bflo(v0.z); accA[5] += w0 * bfhi(v0.z);
            accA[6] += w0 * bflo(v0.w); accA[7] += w0 * bfhi(v0.w);
            accB[0] += w1 * bflo(v1.x); accB[1] += w1 * bfhi(v1.x);
            accB[2] += w1 * bflo(v1.y); accB[3] += w1 * bfhi(v1.y);
            accB[4] += w1 * bflo(v1.z); accB[5] += w1 * bfhi(v1.z);
            accB[6] += w1 * bflo(v1.w); accB[7] += w1 * bfhi(v1.w);
        }
        if (jj < cnt) {
            int j0 = s_nbr[jj];
            uint4 v0 = hb[(size_t)j0 * (OUT2 / 8) + c8];
            float w0 = s_w[jj];
            accA[0] += w0 * bflo(v0.x); accA[1] += w0 * bfhi(v0.x);
            accA[2] += w0 * bflo(v0.y); accA[3] += w0 * bfhi(v0.y);
            accA[4] += w0 * bflo(v0.z); accA[5] += w0 * bfhi(v0.z);
            accA[6] += w0 * bflo(v0.w); accA[7] += w0 * bfhi(v0.w);
        }
        #pragma unroll
        for (int k = 0; k < 8; k++) s_red[g][k][c8] = accA[k] + accB[k];
        __syncthreads();

        if (t < 16) {
            float inv = 1.0f / s_den;
            float o[8];
            #pragma unroll
            for (int k = 0; k < 8; k++) {
                float ss = 0.0f;
                #pragma unroll
                for (int gg = 0; gg < 8; gg++) ss += s_red[gg][k][t];
                float v = ss * inv + b2[t * 8 + k];
                o[k] = v > 0.0f ? v : 0.01f * v;
            }
            float4* dst = (float4*)&out[(size_t)i * OUT2 + t * 8];
            dst[0] = make_float4(o[0], o[1], o[2], o[3]);
            dst[1] = make_float4(o[4], o[5], o[6], o[7]);
        }
    }
}

// ---------------- launch ----------------
extern "C" void kernel_launch(void* const* d_in, const int* in_sizes, int n_in,
                              void* d_out, int out_size) {
    const float* x   = (const float*)d_in[0];
    const float* adj = (const float*)d_in[1];
    const float* w1  = (const float*)d_in[2];
    const float* as1 = (const float*)d_in[3];
    const float* ad1 = (const float*)d_in[4];
    const float* b1  = (const float*)d_in[5];
    const float* w2  = (const float*)d_in[6];
    const float* as2 = (const float*)d_in[7];
    const float* ad2 = (const float*)d_in[8];
    const float* b2  = (const float*)d_in[9];
    float* out = (float*)d_out;

    float *h1p, *hmidp, *h2p;
    __nv_bfloat162 *h1bp, *h2bp;
    cudaGetSymbolAddress((void**)&h1p,   g_h1);
    cudaGetSymbolAddress((void**)&hmidp, g_hmid);
    cudaGetSymbolAddress((void**)&h2p,   g_h2);
    cudaGetSymbolAddress((void**)&h1bp,  g_h1b);
    cudaGetSymbolAddress((void**)&h2bp,  g_h2b);

    build_csr<<<NN, 256>>>(adj);

    // h1 = x @ w1 : [4096,256] x [256,512]  (+ bf16 copy)
    sgemm<128, 128, 8, 8, 8><<<dim3(C1 / 128, NN / 128), 256>>>(
        x, w1, h1p, h1bp, NN, C1, FIN);

    scores1<<<NN, C1>>>(as1, ad1);
    agg1<<<NN, C1>>>(b1);

    // h2 = hmid @ w2 : [4096,512] x [512,128]  (+ bf16 copy)
    sgemm<64, 64, 16, 4, 4><<<dim3(OUT2 / 64, NN / 64), 256>>>(
        hmidp, w2, h2p, h2bp, NN, OUT2, C1);

    scores2<<<NN, OUT2>>>(as2, ad2);
    agg2<<<NN, OUT2>>>(b2, out);
}

// round 10
// speedup vs baseline: 2.3086x; 1.3619x over previous
#include <cuda_runtime.h>
#include <cuda_bf16.h>

#define NN   4096
#define FIN  256
#define C1   512     // H1 * HID
#define H1   8
#define HID  64
#define OUT2 128
#define MAXN 512
#define WPAD (MAXN + 4)

// ---------------- scratch (no allocations allowed) ----------------
__device__ float g_h1[NN * C1];          // layer-1 features fp32 (for scores)
__device__ uint4 g_h1b[NN * C1 / 8];     // layer-1 features bf16 (for gather)
__device__ float g_hmid[NN * C1];        // layer-1 output fp32
__device__ float g_h2[NN * OUT2];        // layer-2 features fp32 (for scores)
__device__ uint4 g_h2b[NN * OUT2 / 8];   // layer-2 features bf16 (for gather)
__device__ float g_asrc1[NN * H1];
__device__ float g_adst1[NN * H1];
__device__ float g_asrc2[NN];
__device__ float g_adst2[NN];
__device__ unsigned short g_nbr[NN * MAXN];
__device__ int g_cnt[NN];

__device__ __forceinline__ float bflo(unsigned u) { return __uint_as_float(u << 16); }
__device__ __forceinline__ float bfhi(unsigned u) { return __uint_as_float(u & 0xffff0000u); }

__device__ __forceinline__ unsigned f2tf(float f) {
    unsigned u; asm("cvt.rna.tf32.f32 %0, %1;" : "=r"(u) : "f"(f)); return u;
}

#define MMA_TF32(d, a, b)                                                  \
    asm volatile(                                                          \
        "mma.sync.aligned.m16n8k8.row.col.f32.tf32.tf32.f32 "              \
        "{%0,%1,%2,%3}, {%4,%5,%6,%7}, {%8,%9}, {%0,%1,%2,%3};"            \
        : "+f"(d[0]), "+f"(d[1]), "+f"(d[2]), "+f"(d[3])                   \
        : "r"(a[0]), "r"(a[1]), "r"(a[2]), "r"(a[3]), "r"(b[0]), "r"(b[1]))

// ---------------- CSR build (deterministic, ordered) ----------------
__global__ void build_csr(const float* __restrict__ adj) {
    int row = blockIdx.x;
    int t   = threadIdx.x;                 // 256
    const float* arow = adj + (size_t)row * NN;
    int base = t * 16;

    float av[16];
    #pragma unroll
    for (int q = 0; q < 4; q++) {
        float4 v = *(const float4*)(arow + base + q * 4);
        av[q * 4 + 0] = v.x; av[q * 4 + 1] = v.y;
        av[q * 4 + 2] = v.z; av[q * 4 + 3] = v.w;
    }
    int cnt = 0;
    #pragma unroll
    for (int k = 0; k < 16; k++) cnt += (av[k] != 0.0f);

    __shared__ int s[256];
    s[t] = cnt;
    __syncthreads();
    for (int off = 1; off < 256; off <<= 1) {
        int v = (t >= off) ? s[t - off] : 0;
        __syncthreads();
        s[t] += v;
        __syncthreads();
    }
    int pos = s[t] - cnt;
    unsigned short* out = g_nbr + (size_t)row * MAXN;
    #pragma unroll
    for (int k = 0; k < 16; k++) {
        if (av[k] != 0.0f) {
            if (pos < MAXN) out[pos] = (unsigned short)(base + k);
            pos++;
        }
    }
    if (t == 255) g_cnt[row] = (s[255] < MAXN) ? s[255] : MAXN;
}

// ---------- tf32 tensor-core GEMM: C = A[MxK] * B[KxN] (+ bf16 copy) ----------
// 256 threads = 8 warps laid out (BM/WM) x (BN/WN); warp tile WM x WN.
// MT = WM/16 m16-tiles, NT = WN/8 n8-tiles, BK = 32 (4 k8 steps per stage).
template <int BM, int BN, int WM, int WN, int MT, int NT>
__global__ __launch_bounds__(256) void gemm_tf32(
    const float* __restrict__ A, const float* __restrict__ B,
    float* __restrict__ C, __nv_bfloat162* __restrict__ Cb,
    int M, int N, int K)
{
    const int BK = 32;
    __shared__ unsigned As[BM][36];        // [m][k], stride 36 -> conflict-free frags
    __shared__ unsigned Bs[BK][BN + 8];    // [k][n], stride BN+8 -> conflict-free frags
    int tid  = threadIdx.x;
    int lane = tid & 31;
    int warp = tid >> 5;
    const int WCOLS = BN / WN;
    int wm = (warp / WCOLS) * WM;
    int wn = (warp % WCOLS) * WN;
    int m0 = blockIdx.y * BM, n0 = blockIdx.x * BN;
    int g = lane >> 2, t4 = lane & 3;

    float acc[MT][NT][4];
    #pragma unroll
    for (int mt = 0; mt < MT; mt++)
        #pragma unroll
        for (int nt = 0; nt < NT; nt++)
            #pragma unroll
            for (int q = 0; q < 4; q++) acc[mt][nt][q] = 0.0f;

    const int A4T = BM / 32;   // float4 A loads per thread
    const int B4T = BN / 32;   // float4 B loads per thread
    float4 pa[A4T], pb[B4T];

    // preload stage 0
    #pragma unroll
    for (int i = 0; i < A4T; i++) {
        int idx = tid + i * 256;
        pa[i] = *(const float4*)&A[(size_t)(m0 + (idx >> 3)) * K + (idx & 7) * 4];
    }
    #pragma unroll
    for (int i = 0; i < B4T; i++) {
        int idx = tid + i * 256;
        pb[i] = *(const float4*)&B[(size_t)(idx / (BN / 4)) * N + n0 + (idx % (BN / 4)) * 4];
    }

    for (int kt = 0; kt < K; kt += BK) {
        // commit prefetched tiles to smem (tf32-rounded)
        #pragma unroll
        for (int i = 0; i < A4T; i++) {
            int idx = tid + i * 256;
            uint4 u = make_uint4(f2tf(pa[i].x), f2tf(pa[i].y), f2tf(pa[i].z), f2tf(pa[i].w));
            *(uint4*)&As[idx >> 3][(idx & 7) * 4] = u;
        }
        #pragma unroll
        for (int i = 0; i < B4T; i++) {
            int idx = tid + i * 256;
            uint4 u = make_uint4(f2tf(pb[i].x), f2tf(pb[i].y), f2tf(pb[i].z), f2tf(pb[i].w));
            *(uint4*)&Bs[idx / (BN / 4)][(idx % (BN / 4)) * 4] = u;
        }
        __syncthreads();

        // prefetch next stage while computing this one
        if (kt + BK < K) {
            #pragma unroll
            for (int i = 0; i < A4T; i++) {
                int idx = tid + i * 256;
                pa[i] = *(const float4*)&A[(size_t)(m0 + (idx >> 3)) * K + kt + BK + (idx & 7) * 4];
            }
            #pragma unroll
            for (int i = 0; i < B4T; i++) {
                int idx = tid + i * 256;
                pb[i] = *(const float4*)&B[(size_t)(kt + BK + idx / (BN / 4)) * N + n0 + (idx % (BN / 4)) * 4];
            }
        }

        #pragma unroll
        for (int ks = 0; ks < 4; ks++) {
            int ko = ks * 8;
            unsigned af[MT][4], bf[NT][2];
            #pragma unroll
            for (int mt = 0; mt < MT; mt++) {
                int r = wm + mt * 16 + g;
                af[mt][0] = As[r][ko + t4];
                af[mt][1] = As[r + 8][ko + t4];
                af[mt][2] = As[r][ko + t4 + 4];
                af[mt][3] = As[r + 8][ko + t4 + 4];
            }
            #pragma unroll
            for (int nt = 0; nt < NT; nt++) {
                int c = wn + nt * 8 + g;
                bf[nt][0] = Bs[ko + t4][c];
                bf[nt][1] = Bs[ko + t4 + 4][c];
            }
            #pragma unroll
            for (int mt = 0; mt < MT; mt++)
                #pragma unroll
                for (int nt = 0; nt < NT; nt++)
                    MMA_TF32(acc[mt][nt], af[mt], bf[nt]);
        }
        __syncthreads();
    }

    // epilogue: fp32 + bf16 copies
    #pragma unroll
    for (int mt = 0; mt < MT; mt++) {
        #pragma unroll
        for (int nt = 0; nt < NT; nt++) {
            int r = m0 + wm + mt * 16 + g;
            int c = n0 + wn + nt * 8 + t4 * 2;
            size_t o0 = (size_t)r * N + c;
            size_t o1 = (size_t)(r + 8) * N + c;
            *(float2*)&C[o0] = make_float2(acc[mt][nt][0], acc[mt][nt][1]);
            *(float2*)&C[o1] = make_float2(acc[mt][nt][2], acc[mt][nt][3]);
            Cb[o0 >> 1] = __floats2bfloat162_rn(acc[mt][nt][0], acc[mt][nt][1]);
            Cb[o1 >> 1] = __floats2bfloat162_rn(acc[mt][nt][2], acc[mt][nt][3]);
        }
    }
}

// ---------------- attention scores, layer 1 ----------------
__global__ void scores1(const float* __restrict__ att_src,
                        const float* __restrict__ att_dst) {
    int n = blockIdx.x;
    int c = threadIdx.x;                  // 512
    __shared__ float ps[C1], pd[C1];
    float hv = g_h1[(size_t)n * C1 + c];
    ps[c] = hv * att_src[c];
    pd[c] = hv * att_dst[c];
    __syncthreads();
    for (int off = 32; off >= 1; off >>= 1) {
        if ((c & 63) < off) { ps[c] += ps[c + off]; pd[c] += pd[c + off]; }
        __syncthreads();
    }
    if ((c & 63) == 0) {
        g_asrc1[n * H1 + (c >> 6)] = ps[c];
        g_adst1[n * H1 + (c >> 6)] = pd[c];
    }
}

// ---------------- attention scores, layer 2 ----------------
__global__ void scores2(const float* __restrict__ att_src,
                        const float* __restrict__ att_dst) {
    int n = blockIdx.x;
    int c = threadIdx.x;                  // 128
    __shared__ float ps[OUT2], pd[OUT2];
    float hv = g_h2[(size_t)n * OUT2 + c];
    ps[c] = hv * att_src[c];
    pd[c] = hv * att_dst[c];
    __syncthreads();
    for (int off = 64; off >= 1; off >>= 1) {
        if (c < off) { ps[c] += ps[c + off]; pd[c] += pd[c + off]; }
        __syncthreads();
    }
    if (c == 0) { g_asrc2[n] = ps[0]; g_adst2[n] = pd[0]; }
}

// ---------------- layer-1 sparse aggregation (bf16 uint4 gather) ----------------
__global__ void __launch_bounds__(512) agg1(const float* __restrict__ b1) {
    int i = blockIdx.x;
    int t = threadIdx.x;                  // 512
    __shared__ unsigned short s_nbr[MAXN];
    __shared__ float s_w[H1][WPAD];
    __shared__ float s_part[H1 * 64];
    __shared__ float s_den[H1];
    __shared__ float s_red[8][8][64];     // [group][k][c8] 16KB

    int cnt = g_cnt[i];
    for (int jj = t; jj < cnt; jj += 512) s_nbr[jj] = g_nbr[(size_t)i * MAXN + jj];
    __syncthreads();

    // phase 1: edge weights
    float adst[H1];
    {
        float4 d0 = *(const float4*)&g_adst1[i * H1];
        float4 d1 = *(const float4*)&g_adst1[i * H1 + 4];
        adst[0] = d0.x; adst[1] = d0.y; adst[2] = d0.z; adst[3] = d0.w;
        adst[4] = d1.x; adst[5] = d1.y; adst[6] = d1.z; adst[7] = d1.w;
    }
    for (int jj = t; jj < cnt; jj += 512) {
        int j = s_nbr[jj];
        float4 a0 = *(const float4*)&g_asrc1[j * H1];
        float4 a1 = *(const float4*)&g_asrc1[j * H1 + 4];
        float av[H1] = {a0.x, a0.y, a0.z, a0.w, a1.x, a1.y, a1.z, a1.w};
        #pragma unroll
        for (int h = 0; h < H1; h++) {
            float v = av[h] + adst[h];
            v = v > 0.0f ? v : 0.2f * v;
            s_w[h][jj] = __expf(v);
        }
    }
    __syncthreads();

    // denominator per head
    {
        int h = t >> 6, k = t & 63;
        float s = 0.0f;
        for (int jj = k; jj < cnt; jj += 64) s += s_w[h][jj];
        s_part[t] = s;
        __syncthreads();
        for (int off = 32; off >= 1; off >>= 1) {
            if (k < off) s_part[t] += s_part[t + off];
            __syncthreads();
        }
        if (k == 0) s_den[h] = s_part[t];
        __syncthreads();
    }

    // phase 2: bf16 gather. lane c8 covers channels [c8*8, c8*8+8); 8 edge groups
    {
        int c8 = t & 63;
        int g  = t >> 6;                  // 0..7
        int h  = c8 >> 3;
        const float* wrow = s_w[h];
        float acc[8] = {0, 0, 0, 0, 0, 0, 0, 0};
        for (int jj = g; jj < cnt; jj += 8) {
            int j = s_nbr[jj];
            uint4 v = g_h1b[(size_t)j * (C1 / 8) + c8];
            float w = wrow[jj];
            acc[0] += w * bflo(v.x); acc[1] += w * bfhi(v.x);
            acc[2] += w * bflo(v.y); acc[3] += w * bfhi(v.y);
            acc[4] += w * bflo(v.z); acc[5] += w * bfhi(v.z);
            acc[6] += w * bflo(v.w); acc[7] += w * bfhi(v.w);
        }
        #pragma unroll
        for (int k = 0; k < 8; k++) s_red[g][k][c8] = acc[k];
        __syncthreads();

        if (t < 64) {
            float inv = 1.0f / s_den[t >> 3];
            float o[8];
            #pragma unroll
            for (int k = 0; k < 8; k++) {
                float s = 0.0f;
                #pragma unroll
                for (int gg = 0; gg < 8; gg++) s += s_red[gg][k][t];
                float v = s * inv + b1[t * 8 + k];
                o[k] = v > 0.0f ? v : 0.01f * v;
            }
            float4* dst = (float4*)&g_hmid[(size_t)i * C1 + t * 8];
            dst[0] = make_float4(o[0], o[1], o[2], o[3]);
            dst[1] = make_float4(o[4], o[5], o[6], o[7]);
        }
    }
}

// ---------------- layer-2 sparse aggregation (bf16 uint4 gather) ----------------
__global__ void __launch_bounds__(128) agg2(const float* __restrict__ b2,
                                            float* __restrict__ out) {
    int i = blockIdx.x;
    int t = threadIdx.x;                  // 128
    __shared__ unsigned short s_nbr[MAXN];
    __shared__ float s_w[MAXN];
    __shared__ float s_part[OUT2];
    __shared__ float s_den;
    __shared__ float s_red[8][8][16];     // 4KB

    int cnt = g_cnt[i];
    for (int jj = t; jj < cnt; jj += 128) s_nbr[jj] = g_nbr[(size_t)i * MAXN + jj];
    __syncthreads();

    float adst = g_adst2[i];
    for (int jj = t; jj < cnt; jj += 128) {
        float v = g_asrc2[s_nbr[jj]] + adst;
        v = v > 0.0f ? v : 0.2f * v;
        s_w[jj] = __expf(v);
    }
    __syncthreads();

    float s = 0.0f;
    for (int jj = t; jj < cnt; jj += 128) s += s_w[jj];
    s_part[t] = s;
    __syncthreads();
    for (int off = 64; off >= 1; off >>= 1) {
        if (t < off) s_part[t] += s_part[t + off];
        __syncthreads();
    }
    if (t == 0) s_den = s_part[0];
    __syncthreads();

    // bf16 gather: lane c8 covers channels [c8*8, c8*8+8); 8 edge groups
    {
        int c8 = t & 15;
        int g  = t >> 4;                  // 0..7
        float acc[8] = {0, 0, 0, 0, 0, 0, 0, 0};
        for (int jj = g; jj < cnt; jj += 8) {
            int j = s_nbr[jj];
            uint4 v = g_h2b[(size_t)j * (OUT2 / 8) + c8];
            float w = s_w[jj];
            acc[0] += w * bflo(v.x); acc[1] += w * bfhi(v.x);
            acc[2] += w * bflo(v.y); acc[3] += w * bfhi(v.y);
            acc[4] += w * bflo(v.z); acc[5] += w * bfhi(v.z);
            acc[6] += w * bflo(v.w); acc[7] += w * bfhi(v.w);
        }
        #pragma unroll
        for (int k = 0; k < 8; k++) s_red[g][k][c8] = acc[k];
        __syncthreads();

        if (t < 16) {
            float inv = 1.0f / s_den;
            float o[8];
            #pragma unroll
            for (int k = 0; k < 8; k++) {
                float ss = 0.0f;
                #pragma unroll
                for (int gg = 0; gg < 8; gg++) ss += s_red[gg][k][t];
                float v = ss * inv + b2[t * 8 + k];
                o[k] = v > 0.0f ? v : 0.01f * v;
            }
            float4* dst = (float4*)&out[(size_t)i * OUT2 + t * 8];
            dst[0] = make_float4(o[0], o[1], o[2], o[3]);
            dst[1] = make_float4(o[4], o[5], o[6], o[7]);
        }
    }
}

// ---------------- launch ----------------
extern "C" void kernel_launch(void* const* d_in, const int* in_sizes, int n_in,
                              void* d_out, int out_size) {
    const float* x   = (const float*)d_in[0];
    const float* adj = (const float*)d_in[1];
    const float* w1  = (const float*)d_in[2];
    const float* as1 = (const float*)d_in[3];
    const float* ad1 = (const float*)d_in[4];
    const float* b1  = (const float*)d_in[5];
    const float* w2  = (const float*)d_in[6];
    const float* as2 = (const float*)d_in[7];
    const float* ad2 = (const float*)d_in[8];
    const float* b2  = (const float*)d_in[9];
    float* out = (float*)d_out;

    float *h1p, *hmidp, *h2p;
    __nv_bfloat162 *h1bp, *h2bp;
    cudaGetSymbolAddress((void**)&h1p,   g_h1);
    cudaGetSymbolAddress((void**)&hmidp, g_hmid);
    cudaGetSymbolAddress((void**)&h2p,   g_h2);
    cudaGetSymbolAddress((void**)&h1bp,  g_h1b);
    cudaGetSymbolAddress((void**)&h2bp,  g_h2b);

    build_csr<<<NN, 256>>>(adj);

    // h1 = x @ w1 : [4096,256] x [256,512]  (tf32 MMA, + bf16 copy)
    gemm_tf32<128, 128, 64, 32, 4, 4><<<dim3(C1 / 128, NN / 128), 256>>>(
        x, w1, h1p, h1bp, NN, C1, FIN);

    scores1<<<NN, C1>>>(as1, ad1);
    agg1<<<NN, C1>>>(b1);

    // h2 = hmid @ w2 : [4096,512] x [512,128]  (tf32 MMA, + bf16 copy)
    gemm_tf32<64, 64, 32, 16, 2, 2><<<dim3(OUT2 / 64, NN / 64), 256>>>(
        hmidp, w2, h2p, h2bp, NN, OUT2, C1);

    scores2<<<NN, OUT2>>>(as2, ad2);
    agg2<<<NN, OUT2>>>(b2, out);
}

// round 11
// speedup vs baseline: 2.4520x; 1.0621x over previous
#include <cuda_runtime.h>
#include <cuda_bf16.h>

#define NN   4096
#define FIN  256
#define C1   512     // H1 * HID
#define H1   8
#define HID  64
#define OUT2 128
#define MAXN 512
#define WPAD (MAXN + 4)

// ---------------- scratch (no allocations allowed) ----------------
__device__ float g_h1[NN * C1];          // layer-1 features fp32
__device__ uint4 g_h1b[NN * C1 / 8];     // layer-1 features bf16 (gather)
__device__ float g_hmid[NN * C1];        // layer-1 output fp32
__device__ float g_h2[NN * OUT2];        // layer-2 features fp32
__device__ uint4 g_h2b[NN * OUT2 / 8];   // layer-2 features bf16 (gather)
__device__ float g_asrc1[NN * H1];
__device__ float g_adst1[NN * H1];
__device__ float g_asrc2[NN];
__device__ float g_adst2[NN];
__device__ float g_p2s[2 * NN];          // gemm2 score partials
__device__ float g_p2d[2 * NN];
__device__ unsigned short g_nbr[NN * MAXN];
__device__ int g_cnt[NN];

__device__ __forceinline__ float bflo(unsigned u) { return __uint_as_float(u << 16); }
__device__ __forceinline__ float bfhi(unsigned u) { return __uint_as_float(u & 0xffff0000u); }

__device__ __forceinline__ unsigned f2tf(float f) {
    unsigned u; asm("cvt.rna.tf32.f32 %0, %1;" : "=r"(u) : "f"(f)); return u;
}

#define MMA_TF32(d, a, b)                                                  \
    asm volatile(                                                          \
        "mma.sync.aligned.m16n8k8.row.col.f32.tf32.tf32.f32 "              \
        "{%0,%1,%2,%3}, {%4,%5,%6,%7}, {%8,%9}, {%0,%1,%2,%3};"            \
        : "+f"(d[0]), "+f"(d[1]), "+f"(d[2]), "+f"(d[3])                   \
        : "r"(a[0]), "r"(a[1]), "r"(a[2]), "r"(a[3]), "r"(b[0]), "r"(b[1]))

// ---------------- CSR build (deterministic, ordered) ----------------
__global__ void build_csr(const float* __restrict__ adj) {
    int row = blockIdx.x;
    int t   = threadIdx.x;                 // 256
    const float* arow = adj + (size_t)row * NN;
    int base = t * 16;

    float av[16];
    #pragma unroll
    for (int q = 0; q < 4; q++) {
        float4 v = *(const float4*)(arow + base + q * 4);
        av[q * 4 + 0] = v.x; av[q * 4 + 1] = v.y;
        av[q * 4 + 2] = v.z; av[q * 4 + 3] = v.w;
    }
    int cnt = 0;
    #pragma unroll
    for (int k = 0; k < 16; k++) cnt += (av[k] != 0.0f);

    __shared__ int s[256];
    s[t] = cnt;
    __syncthreads();
    for (int off = 1; off < 256; off <<= 1) {
        int v = (t >= off) ? s[t - off] : 0;
        __syncthreads();
        s[t] += v;
        __syncthreads();
    }
    int pos = s[t] - cnt;
    unsigned short* out = g_nbr + (size_t)row * MAXN;
    #pragma unroll
    for (int k = 0; k < 16; k++) {
        if (av[k] != 0.0f) {
            if (pos < MAXN) out[pos] = (unsigned short)(base + k);
            pos++;
        }
    }
    if (t == 255) g_cnt[row] = (s[255] < MAXN) ? s[255] : MAXN;
}

// ---------- tf32 tensor-core GEMM + fused attention-score epilogue ----------
// 256 threads = 8 warps (BM/WM rows x BN/WN cols). BK=32.
// NSEG 64-col score segments per block; DIRECT: write g_asrc/adst [row*H1+head],
// else per-block partials sA[(bx*NSEG+seg)*NN + row].
template <int BM, int BN, int WM, int WN, int MT, int NT, int NSEG, bool DIRECT>
__global__ __launch_bounds__(256) void gemm_tf32(
    const float* __restrict__ A, const float* __restrict__ B,
    float* __restrict__ C, __nv_bfloat162* __restrict__ Cb,
    const float* __restrict__ att_s, const float* __restrict__ att_d,
    float* __restrict__ sA, float* __restrict__ sD,
    int M, int N, int K)
{
    const int BK = 32;
    const int WCOLS = BN / WN;
    const int WPS = WCOLS / NSEG;          // warps per score segment
    __shared__ unsigned As[BM][36];
    __shared__ unsigned Bs[BK][BN + 8];
    __shared__ float s_ss[BM][WCOLS];
    __shared__ float s_dd[BM][WCOLS];
    int tid  = threadIdx.x;
    int lane = tid & 31;
    int warp = tid >> 5;
    int wx = warp % WCOLS, wy = warp / WCOLS;
    int wm = wy * WM;
    int wn = wx * WN;
    int m0 = blockIdx.y * BM, n0 = blockIdx.x * BN;
    int g = lane >> 2, t4 = lane & 3;

    float acc[MT][NT][4];
    #pragma unroll
    for (int mt = 0; mt < MT; mt++)
        #pragma unroll
        for (int nt = 0; nt < NT; nt++)
            #pragma unroll
            for (int q = 0; q < 4; q++) acc[mt][nt][q] = 0.0f;

    const int A4T = BM / 32;
    const int B4T = BN / 32;
    float4 pa[A4T], pb[B4T];

    #pragma unroll
    for (int i = 0; i < A4T; i++) {
        int idx = tid + i * 256;
        pa[i] = *(const float4*)&A[(size_t)(m0 + (idx >> 3)) * K + (idx & 7) * 4];
    }
    #pragma unroll
    for (int i = 0; i < B4T; i++) {
        int idx = tid + i * 256;
        pb[i] = *(const float4*)&B[(size_t)(idx / (BN / 4)) * N + n0 + (idx % (BN / 4)) * 4];
    }

    for (int kt = 0; kt < K; kt += BK) {
        #pragma unroll
        for (int i = 0; i < A4T; i++) {
            int idx = tid + i * 256;
            uint4 u = make_uint4(f2tf(pa[i].x), f2tf(pa[i].y), f2tf(pa[i].z), f2tf(pa[i].w));
            *(uint4*)&As[idx >> 3][(idx & 7) * 4] = u;
        }
        #pragma unroll
        for (int i = 0; i < B4T; i++) {
            int idx = tid + i * 256;
            uint4 u = make_uint4(f2tf(pb[i].x), f2tf(pb[i].y), f2tf(pb[i].z), f2tf(pb[i].w));
            *(uint4*)&Bs[idx / (BN / 4)][(idx % (BN / 4)) * 4] = u;
        }
        __syncthreads();

        if (kt + BK < K) {
            #pragma unroll
            for (int i = 0; i < A4T; i++) {
                int idx = tid + i * 256;
                pa[i] = *(const float4*)&A[(size_t)(m0 + (idx >> 3)) * K + kt + BK + (idx & 7) * 4];
            }
            #pragma unroll
            for (int i = 0; i < B4T; i++) {
                int idx = tid + i * 256;
                pb[i] = *(const float4*)&B[(size_t)(kt + BK + idx / (BN / 4)) * N + n0 + (idx % (BN / 4)) * 4];
            }
        }

        #pragma unroll
        for (int ks = 0; ks < 4; ks++) {
            int ko = ks * 8;
            unsigned af[MT][4], bf[NT][2];
            #pragma unroll
            for (int mt = 0; mt < MT; mt++) {
                int r = wm + mt * 16 + g;
                af[mt][0] = As[r][ko + t4];
                af[mt][1] = As[r + 8][ko + t4];
                af[mt][2] = As[r][ko + t4 + 4];
                af[mt][3] = As[r + 8][ko + t4 + 4];
            }
            #pragma unroll
            for (int nt = 0; nt < NT; nt++) {
                int c = wn + nt * 8 + g;
                bf[nt][0] = Bs[ko + t4][c];
                bf[nt][1] = Bs[ko + t4 + 4][c];
            }
            #pragma unroll
            for (int mt = 0; mt < MT; mt++)
                #pragma unroll
                for (int nt = 0; nt < NT; nt++)
                    MMA_TF32(acc[mt][nt], af[mt], bf[nt]);
        }
        __syncthreads();
    }

    // ---- epilogue: fp32 + bf16 stores ----
    #pragma unroll
    for (int mt = 0; mt < MT; mt++) {
        #pragma unroll
        for (int nt = 0; nt < NT; nt++) {
            int r = m0 + wm + mt * 16 + g;
            int c = n0 + wn + nt * 8 + t4 * 2;
            size_t o0 = (size_t)r * N + c;
            size_t o1 = (size_t)(r + 8) * N + c;
            *(float2*)&C[o0] = make_float2(acc[mt][nt][0], acc[mt][nt][1]);
            *(float2*)&C[o1] = make_float2(acc[mt][nt][2], acc[mt][nt][3]);
            Cb[o0 >> 1] = __floats2bfloat162_rn(acc[mt][nt][0], acc[mt][nt][1]);
            Cb[o1 >> 1] = __floats2bfloat162_rn(acc[mt][nt][2], acc[mt][nt][3]);
        }
    }

    // ---- fused attention scores ----
    float asv[NT][2], adv[NT][2];
    #pragma unroll
    for (int nt = 0; nt < NT; nt++) {
        int c = n0 + wn + nt * 8 + t4 * 2;
        asv[nt][0] = att_s[c]; asv[nt][1] = att_s[c + 1];
        adv[nt][0] = att_d[c]; adv[nt][1] = att_d[c + 1];
    }
    #pragma unroll
    for (int mt = 0; mt < MT; mt++) {
        #pragma unroll
        for (int half = 0; half < 2; half++) {
            float ss = 0.0f, dd = 0.0f;
            #pragma unroll
            for (int nt = 0; nt < NT; nt++) {
                ss += acc[mt][nt][2 * half] * asv[nt][0] + acc[mt][nt][2 * half + 1] * asv[nt][1];
                dd += acc[mt][nt][2 * half] * adv[nt][0] + acc[mt][nt][2 * half + 1] * adv[nt][1];
            }
            #pragma unroll
            for (int off = 1; off < 4; off <<= 1) {
                ss += __shfl_xor_sync(0xffffffffu, ss, off);
                dd += __shfl_xor_sync(0xffffffffu, dd, off);
            }
            if (t4 == 0) {
                int rl = wm + mt * 16 + g + half * 8;
                s_ss[rl][wx] = ss;
                s_dd[rl][wx] = dd;
            }
        }
    }
    __syncthreads();
    for (int idx = tid; idx < BM * NSEG; idx += 256) {
        int rl = idx % BM, seg = idx / BM;
        float ss = 0.0f, dd = 0.0f;
        #pragma unroll
        for (int w = 0; w < WPS; w++) {
            ss += s_ss[rl][seg * WPS + w];
            dd += s_dd[rl][seg * WPS + w];
        }
        if (DIRECT) {
            int h = blockIdx.x * NSEG + seg;
            sA[(size_t)(m0 + rl) * H1 + h] = ss;
            sD[(size_t)(m0 + rl) * H1 + h] = dd;
        } else {
            size_t o = (size_t)(blockIdx.x * NSEG + seg) * NN + m0 + rl;
            sA[o] = ss;
            sD[o] = dd;
        }
    }
}

// ---------------- combine gemm2 score partials ----------------
__global__ void reduce2() {
    int n = blockIdx.x * 256 + threadIdx.x;
    if (n < NN) {
        g_asrc2[n] = g_p2s[n] + g_p2s[NN + n];
        g_adst2[n] = g_p2d[n] + g_p2d[NN + n];
    }
}

// ---------------- layer-1 sparse aggregation (bf16 uint4 gather) ----------------
__global__ void __launch_bounds__(512) agg1(const float* __restrict__ b1) {
    int i = blockIdx.x;
    int t = threadIdx.x;                  // 512
    __shared__ unsigned short s_nbr[MAXN];
    __shared__ float s_w[H1][WPAD];
    __shared__ float s_part[H1 * 64];
    __shared__ float s_den[H1];
    __shared__ float s_red[8][8][64];     // 16KB

    int cnt = g_cnt[i];
    for (int jj = t; jj < cnt; jj += 512) s_nbr[jj] = g_nbr[(size_t)i * MAXN + jj];
    __syncthreads();

    float adst[H1];
    {
        float4 d0 = *(const float4*)&g_adst1[i * H1];
        float4 d1 = *(const float4*)&g_adst1[i * H1 + 4];
        adst[0] = d0.x; adst[1] = d0.y; adst[2] = d0.z; adst[3] = d0.w;
        adst[4] = d1.x; adst[5] = d1.y; adst[6] = d1.z; adst[7] = d1.w;
    }
    for (int jj = t; jj < cnt; jj += 512) {
        int j = s_nbr[jj];
        float4 a0 = *(const float4*)&g_asrc1[j * H1];
        float4 a1 = *(const float4*)&g_asrc1[j * H1 + 4];
        float av[H1] = {a0.x, a0.y, a0.z, a0.w, a1.x, a1.y, a1.z, a1.w};
        #pragma unroll
        for (int h = 0; h < H1; h++) {
            float v = av[h] + adst[h];
            v = v > 0.0f ? v : 0.2f * v;
            s_w[h][jj] = __expf(v);
        }
    }
    __syncthreads();

    {
        int h = t >> 6, k = t & 63;
        float s = 0.0f;
        for (int jj = k; jj < cnt; jj += 64) s += s_w[h][jj];
        s_part[t] = s;
        __syncthreads();
        for (int off = 32; off >= 1; off >>= 1) {
            if (k < off) s_part[t] += s_part[t + off];
            __syncthreads();
        }
        if (k == 0) s_den[h] = s_part[t];
        __syncthreads();
    }

    {
        int c8 = t & 63;
        int g  = t >> 6;                  // 0..7
        int h  = c8 >> 3;
        const float* wrow = s_w[h];
        float acc[8] = {0, 0, 0, 0, 0, 0, 0, 0};
        for (int jj = g; jj < cnt; jj += 8) {
            int j = s_nbr[jj];
            uint4 v = g_h1b[(size_t)j * (C1 / 8) + c8];
            float w = wrow[jj];
            acc[0] += w * bflo(v.x); acc[1] += w * bfhi(v.x);
            acc[2] += w * bflo(v.y); acc[3] += w * bfhi(v.y);
            acc[4] += w * bflo(v.z); acc[5] += w * bfhi(v.z);
            acc[6] += w * bflo(v.w); acc[7] += w * bfhi(v.w);
        }
        #pragma unroll
        for (int k = 0; k < 8; k++) s_red[g][k][c8] = acc[k];
        __syncthreads();

        if (t < 64) {
            float inv = 1.0f / s_den[t >> 3];
            float o[8];
            #pragma unroll
            for (int k = 0; k < 8; k++) {
                float s = 0.0f;
                #pragma unroll
                for (int gg = 0; gg < 8; gg++) s += s_red[gg][k][t];
                float v = s * inv + b1[t * 8 + k];
                o[k] = v > 0.0f ? v : 0.01f * v;
            }
            float4* dst = (float4*)&g_hmid[(size_t)i * C1 + t * 8];
            dst[0] = make_float4(o[0], o[1], o[2], o[3]);
            dst[1] = make_float4(o[4], o[5], o[6], o[7]);
        }
    }
}

// ---------------- layer-2 sparse aggregation (256 thr, 16 groups) ----------------
__global__ void __launch_bounds__(256) agg2(const float* __restrict__ b2,
                                            float* __restrict__ out) {
    int i = blockIdx.x;
    int t = threadIdx.x;                  // 256
    __shared__ unsigned short s_nbr[MAXN];
    __shared__ float s_w[MAXN];
    __shared__ float s_part[256];
    __shared__ float s_den;
    __shared__ float s_red[16][8][16];    // 8KB

    int cnt = g_cnt[i];
    for (int jj = t; jj < cnt; jj += 256) s_nbr[jj] = g_nbr[(size_t)i * MAXN + jj];
    __syncthreads();

    float adst = g_adst2[i];
    for (int jj = t; jj < cnt; jj += 256) {
        float v = g_asrc2[s_nbr[jj]] + adst;
        v = v > 0.0f ? v : 0.2f * v;
        s_w[jj] = __expf(v);
    }
    __syncthreads();

    float s = 0.0f;
    for (int jj = t; jj < cnt; jj += 256) s += s_w[jj];
    s_part[t] = s;
    __syncthreads();
    for (int off = 128; off >= 1; off >>= 1) {
        if (t < off) s_part[t] += s_part[t + off];
        __syncthreads();
    }
    if (t == 0) s_den = s_part[0];
    __syncthreads();

    {
        int c8 = t & 15;
        int g  = t >> 4;                  // 0..15
        float acc[8] = {0, 0, 0, 0, 0, 0, 0, 0};
        for (int jj = g; jj < cnt; jj += 16) {
            int j = s_nbr[jj];
            uint4 v = g_h2b[(size_t)j * (OUT2 / 8) + c8];
            float w = s_w[jj];
            acc[0] += w * bflo(v.x); acc[1] += w * bfhi(v.x);
            acc[2] += w * bflo(v.y); acc[3] += w * bfhi(v.y);
            acc[4] += w * bflo(v.z); acc[5] += w * bfhi(v.z);
            acc[6] += w * bflo(v.w); acc[7] += w * bfhi(v.w);
        }
        #pragma unroll
        for (int k = 0; k < 8; k++) s_red[g][k][c8] = acc[k];
        __syncthreads();

        if (t < 16) {
            float inv = 1.0f / s_den;
            float o[8];
            #pragma unroll
            for (int k = 0; k < 8; k++) {
                float ss = 0.0f;
                #pragma unroll
                for (int gg = 0; gg < 16; gg++) ss += s_red[gg][k][t];
                float v = ss * inv + b2[t * 8 + k];
                o[k] = v > 0.0f ? v : 0.01f * v;
            }
            float4* dst = (float4*)&out[(size_t)i * OUT2 + t * 8];
            dst[0] = make_float4(o[0], o[1], o[2], o[3]);
            dst[1] = make_float4(o[4], o[5], o[6], o[7]);
        }
    }
}

// ---------------- launch ----------------
extern "C" void kernel_launch(void* const* d_in, const int* in_sizes, int n_in,
                              void* d_out, int out_size) {
    const float* x   = (const float*)d_in[0];
    const float* adj = (const float*)d_in[1];
    const float* w1  = (const float*)d_in[2];
    const float* as1 = (const float*)d_in[3];
    const float* ad1 = (const float*)d_in[4];
    const float* b1  = (const float*)d_in[5];
    const float* w2  = (const float*)d_in[6];
    const float* as2 = (const float*)d_in[7];
    const float* ad2 = (const float*)d_in[8];
    const float* b2  = (const float*)d_in[9];
    float* out = (float*)d_out;

    float *h1p, *hmidp, *h2p, *asrc1p, *adst1p, *p2sp, *p2dp;
    __nv_bfloat162 *h1bp, *h2bp;
    cudaGetSymbolAddress((void**)&h1p,    g_h1);
    cudaGetSymbolAddress((void**)&hmidp,  g_hmid);
    cudaGetSymbolAddress((void**)&h2p,    g_h2);
    cudaGetSymbolAddress((void**)&h1bp,   g_h1b);
    cudaGetSymbolAddress((void**)&h2bp,   g_h2b);
    cudaGetSymbolAddress((void**)&asrc1p, g_asrc1);
    cudaGetSymbolAddress((void**)&adst1p, g_adst1);
    cudaGetSymbolAddress((void**)&p2sp,   g_p2s);
    cudaGetSymbolAddress((void**)&p2dp,   g_p2d);

    build_csr<<<NN, 256>>>(adj);

    // h1 = x @ w1 (tf32 MMA, + bf16 copy, + fused scores1)
    gemm_tf32<128, 128, 64, 32, 4, 4, 2, true><<<dim3(C1 / 128, NN / 128), 256>>>(
        x, w1, h1p, h1bp, as1, ad1, asrc1p, adst1p, NN, C1, FIN);

    agg1<<<NN, C1>>>(b1);

    // h2 = hmid @ w2 (tf32 MMA, + bf16 copy, + fused score partials)
    gemm_tf32<64, 64, 32, 16, 2, 2, 1, false><<<dim3(OUT2 / 64, NN / 64), 256>>>(
        hmidp, w2, h2p, h2bp, as2, ad2, p2sp, p2dp, NN, OUT2, C1);

    reduce2<<<NN / 256, 256>>>();

    agg2<<<NN, 256>>>(b2, out);
}

// round 13
// speedup vs baseline: 2.4579x; 1.0024x over previous
#include <cuda_runtime.h>
#include <cuda_bf16.h>

#define NN   4096
#define FIN  256
#define C1   512     // H1 * HID
#define H1   8
#define HID  64
#define OUT2 128
#define MAXN 512
#define WPAD (MAXN + 4)

// ---------------- scratch (no allocations allowed) ----------------
__device__ float g_h1[NN * C1];          // layer-1 features fp32
__device__ uint4 g_h1b[NN * C1 / 8];     // layer-1 features bf16 (gather)
__device__ float g_hmid[NN * C1];        // layer-1 output fp32
__device__ float g_h2[NN * OUT2];        // layer-2 features fp32
__device__ uint4 g_h2b[NN * OUT2 / 8];   // layer-2 features bf16 (gather)
__device__ float g_asrc1[NN * H1];
__device__ float g_adst1[NN * H1];
__device__ float g_asrc2[NN];
__device__ float g_adst2[NN];
__device__ float g_p2s[2 * NN];          // gemm2 score partials
__device__ float g_p2d[2 * NN];
__device__ unsigned short g_nbr[NN * MAXN];
__device__ int g_cnt[NN];

__device__ __forceinline__ float bflo(unsigned u) { return __uint_as_float(u << 16); }
__device__ __forceinline__ float bfhi(unsigned u) { return __uint_as_float(u & 0xffff0000u); }

__device__ __forceinline__ unsigned f2tf(float f) {
    unsigned u; asm("cvt.rna.tf32.f32 %0, %1;" : "=r"(u) : "f"(f)); return u;
}

#define MMA_TF32(d, a, b)                                                  \
    asm volatile(                                                          \
        "mma.sync.aligned.m16n8k8.row.col.f32.tf32.tf32.f32 "              \
        "{%0,%1,%2,%3}, {%4,%5,%6,%7}, {%8,%9}, {%0,%1,%2,%3};"            \
        : "+f"(d[0]), "+f"(d[1]), "+f"(d[2]), "+f"(d[3])                   \
        : "r"(a[0]), "r"(a[1]), "r"(a[2]), "r"(a[3]), "r"(b[0]), "r"(b[1]))

// ---------------- CSR build (deterministic, ordered) ----------------
__global__ void build_csr(const float* __restrict__ adj) {
    int row = blockIdx.x;
    int t   = threadIdx.x;                 // 256
    const float* arow = adj + (size_t)row * NN;
    int base = t * 16;

    float av[16];
    #pragma unroll
    for (int q = 0; q < 4; q++) {
        float4 v = *(const float4*)(arow + base + q * 4);
        av[q * 4 + 0] = v.x; av[q * 4 + 1] = v.y;
        av[q * 4 + 2] = v.z; av[q * 4 + 3] = v.w;
    }
    int cnt = 0;
    #pragma unroll
    for (int k = 0; k < 16; k++) cnt += (av[k] != 0.0f);

    __shared__ int s[256];
    s[t] = cnt;
    __syncthreads();
    for (int off = 1; off < 256; off <<= 1) {
        int v = (t >= off) ? s[t - off] : 0;
        __syncthreads();
        s[t] += v;
        __syncthreads();
    }
    int pos = s[t] - cnt;
    unsigned short* out = g_nbr + (size_t)row * MAXN;
    #pragma unroll
    for (int k = 0; k < 16; k++) {
        if (av[k] != 0.0f) {
            if (pos < MAXN) out[pos] = (unsigned short)(base + k);
            pos++;
        }
    }
    if (t == 255) g_cnt[row] = (s[255] < MAXN) ? s[255] : MAXN;
}

// ---------- tf32 tensor-core GEMM + fused attention-score epilogue ----------
// 256 threads = 8 warps (BM/WM rows x BN/WN cols). BK=32.
// NSEG 64-col score segments per block; DIRECT: write g_asrc/adst [row*H1+head],
// else per-block partials sA[(bx*NSEG+seg)*NN + row].
template <int BM, int BN, int WM, int WN, int MT, int NT, int NSEG, bool DIRECT>
__global__ __launch_bounds__(256) void gemm_tf32(
    const float* __restrict__ A, const float* __restrict__ B,
    float* __restrict__ C, __nv_bfloat162* __restrict__ Cb,
    const float* __restrict__ att_s, const float* __restrict__ att_d,
    float* __restrict__ sA, float* __restrict__ sD,
    int M, int N, int K)
{
    const int BK = 32;
    const int WCOLS = BN / WN;
    const int WPS = WCOLS / NSEG;          // warps per score segment
    __shared__ unsigned As[BM][36];
    __shared__ unsigned Bs[BK][BN + 8];
    __shared__ float s_ss[BM][WCOLS];
    __shared__ float s_dd[BM][WCOLS];
    int tid  = threadIdx.x;
    int lane = tid & 31;
    int warp = tid >> 5;
    int wx = warp % WCOLS, wy = warp / WCOLS;
    int wm = wy * WM;
    int wn = wx * WN;
    int m0 = blockIdx.y * BM, n0 = blockIdx.x * BN;
    int g = lane >> 2, t4 = lane & 3;

    float acc[MT][NT][4];
    #pragma unroll
    for (int mt = 0; mt < MT; mt++)
        #pragma unroll
        for (int nt = 0; nt < NT; nt++)
            #pragma unroll
            for (int q = 0; q < 4; q++) acc[mt][nt][q] = 0.0f;

    const int A4T = BM / 32;
    const int B4T = BN / 32;
    float4 pa[A4T], pb[B4T];

    #pragma unroll
    for (int i = 0; i < A4T; i++) {
        int idx = tid + i * 256;
        pa[i] = *(const float4*)&A[(size_t)(m0 + (idx >> 3)) * K + (idx & 7) * 4];
    }
    #pragma unroll
    for (int i = 0; i < B4T; i++) {
        int idx = tid + i * 256;
        pb[i] = *(const float4*)&B[(size_t)(idx / (BN / 4)) * N + n0 + (idx % (BN / 4)) * 4];
    }

    for (int kt = 0; kt < K; kt += BK) {
        #pragma unroll
        for (int i = 0; i < A4T; i++) {
            int idx = tid + i * 256;
            uint4 u = make_uint4(f2tf(pa[i].x), f2tf(pa[i].y), f2tf(pa[i].z), f2tf(pa[i].w));
            *(uint4*)&As[idx >> 3][(idx & 7) * 4] = u;
        }
        #pragma unroll
        for (int i = 0; i < B4T; i++) {
            int idx = tid + i * 256;
            uint4 u = make_uint4(f2tf(pb[i].x), f2tf(pb[i].y), f2tf(pb[i].z), f2tf(pb[i].w));
            *(uint4*)&Bs[idx / (BN / 4)][(idx % (BN / 4)) * 4] = u;
        }
        __syncthreads();

        if (kt + BK < K) {
            #pragma unroll
            for (int i = 0; i < A4T; i++) {
                int idx = tid + i * 256;
                pa[i] = *(const float4*)&A[(size_t)(m0 + (idx >> 3)) * K + kt + BK + (idx & 7) * 4];
            }
            #pragma unroll
            for (int i = 0; i < B4T; i++) {
                int idx = tid + i * 256;
                pb[i] = *(const float4*)&B[(size_t)(kt + BK + idx / (BN / 4)) * N + n0 + (idx % (BN / 4)) * 4];
            }
        }

        #pragma unroll
        for (int ks = 0; ks < 4; ks++) {
            int ko = ks * 8;
            unsigned af[MT][4], bf[NT][2];
            #pragma unroll
            for (int mt = 0; mt < MT; mt++) {
                int r = wm + mt * 16 + g;
                af[mt][0] = As[r][ko + t4];
                af[mt][1] = As[r + 8][ko + t4];
                af[mt][2] = As[r][ko + t4 + 4];
                af[mt][3] = As[r + 8][ko + t4 + 4];
            }
            #pragma unroll
            for (int nt = 0; nt < NT; nt++) {
                int c = wn + nt * 8 + g;
                bf[nt][0] = Bs[ko + t4][c];
                bf[nt][1] = Bs[ko + t4 + 4][c];
            }
            #pragma unroll
            for (int mt = 0; mt < MT; mt++)
                #pragma unroll
                for (int nt = 0; nt < NT; nt++)
                    MMA_TF32(acc[mt][nt], af[mt], bf[nt]);
        }
        __syncthreads();
    }

    // ---- epilogue: fp32 + bf16 stores ----
    #pragma unroll
    for (int mt = 0; mt < MT; mt++) {
        #pragma unroll
        for (int nt = 0; nt < NT; nt++) {
            int r = m0 + wm + mt * 16 + g;
            int c = n0 + wn + nt * 8 + t4 * 2;
            size_t o0 = (size_t)r * N + c;
            size_t o1 = (size_t)(r + 8) * N + c;
            *(float2*)&C[o0] = make_float2(acc[mt][nt][0], acc[mt][nt][1]);
            *(float2*)&C[o1] = make_float2(acc[mt][nt][2], acc[mt][nt][3]);
            Cb[o0 >> 1] = __floats2bfloat162_rn(acc[mt][nt][0], acc[mt][nt][1]);
            Cb[o1 >> 1] = __floats2bfloat162_rn(acc[mt][nt][2], acc[mt][nt][3]);
        }
    }

    // ---- fused attention scores ----
    float asv[NT][2], adv[NT][2];
    #pragma unroll
    for (int nt = 0; nt < NT; nt++) {
        int c = n0 + wn + nt * 8 + t4 * 2;
        asv[nt][0] = att_s[c]; asv[nt][1] = att_s[c + 1];
        adv[nt][0] = att_d[c]; adv[nt][1] = att_d[c + 1];
    }
    #pragma unroll
    for (int mt = 0; mt < MT; mt++) {
        #pragma unroll
        for (int half = 0; half < 2; half++) {
            float ss = 0.0f, dd = 0.0f;
            #pragma unroll
            for (int nt = 0; nt < NT; nt++) {
                ss += acc[mt][nt][2 * half] * asv[nt][0] + acc[mt][nt][2 * half + 1] * asv[nt][1];
                dd += acc[mt][nt][2 * half] * adv[nt][0] + acc[mt][nt][2 * half + 1] * adv[nt][1];
            }
            #pragma unroll
            for (int off = 1; off < 4; off <<= 1) {
                ss += __shfl_xor_sync(0xffffffffu, ss, off);
                dd += __shfl_xor_sync(0xffffffffu, dd, off);
            }
            if (t4 == 0) {
                int rl = wm + mt * 16 + g + half * 8;
                s_ss[rl][wx] = ss;
                s_dd[rl][wx] = dd;
            }
        }
    }
    __syncthreads();
    for (int idx = tid; idx < BM * NSEG; idx += 256) {
        int rl = idx % BM, seg = idx / BM;
        float ss = 0.0f, dd = 0.0f;
        #pragma unroll
        for (int w = 0; w < WPS; w++) {
            ss += s_ss[rl][seg * WPS + w];
            dd += s_dd[rl][seg * WPS + w];
        }
        if (DIRECT) {
            int h = blockIdx.x * NSEG + seg;
            sA[(size_t)(m0 + rl) * H1 + h] = ss;
            sD[(size_t)(m0 + rl) * H1 + h] = dd;
        } else {
            size_t o = (size_t)(blockIdx.x * NSEG + seg) * NN + m0 + rl;
            sA[o] = ss;
            sD[o] = dd;
        }
    }
}

// ---------------- combine gemm2 score partials ----------------
__global__ void reduce2() {
    int n = blockIdx.x * 256 + threadIdx.x;
    if (n < NN) {
        g_asrc2[n] = g_p2s[n] + g_p2s[NN + n];
        g_adst2[n] = g_p2d[n] + g_p2d[NN + n];
    }
}

// ---------------- layer-1 sparse aggregation (bf16 uint4 gather) ----------------
__global__ void __launch_bounds__(512) agg1(const float* __restrict__ b1) {
    int i = blockIdx.x;
    int t = threadIdx.x;                  // 512
    __shared__ unsigned short s_nbr[MAXN];
    __shared__ float s_w[H1][WPAD];
    __shared__ float s_part[H1 * 64];
    __shared__ float s_den[H1];
    __shared__ float s_red[8][8][64];     // 16KB

    int cnt = g_cnt[i];
    for (int jj = t; jj < cnt; jj += 512) s_nbr[jj] = g_nbr[(size_t)i * MAXN + jj];
    __syncthreads();

    float adst[H1];
    {
        float4 d0 = *(const float4*)&g_adst1[i * H1];
        float4 d1 = *(const float4*)&g_adst1[i * H1 + 4];
        adst[0] = d0.x; adst[1] = d0.y; adst[2] = d0.z; adst[3] = d0.w;
        adst[4] = d1.x; adst[5] = d1.y; adst[6] = d1.z; adst[7] = d1.w;
    }
    for (int jj = t; jj < cnt; jj += 512) {
        int j = s_nbr[jj];
        float4 a0 = *(const float4*)&g_asrc1[j * H1];
        float4 a1 = *(const float4*)&g_asrc1[j * H1 + 4];
        float av[H1] = {a0.x, a0.y, a0.z, a0.w, a1.x, a1.y, a1.z, a1.w};
        #pragma unroll
        for (int h = 0; h < H1; h++) {
            float v = av[h] + adst[h];
            v = v > 0.0f ? v : 0.2f * v;
            s_w[h][jj] = __expf(v);
        }
    }
    __syncthreads();

    {
        int h = t >> 6, k = t & 63;
        float s = 0.0f;
        for (int jj = k; jj < cnt; jj += 64) s += s_w[h][jj];
        s_part[t] = s;
        __syncthreads();
        for (int off = 32; off >= 1; off >>= 1) {
            if (k < off) s_part[t] += s_part[t + off];
            __syncthreads();
        }
        if (k == 0) s_den[h] = s_part[t];
        __syncthreads();
    }

    {
        int c8 = t & 63;
        int g  = t >> 6;                  // 0..7
        int h  = c8 >> 3;
        const float* wrow = s_w[h];
        float acc[8] = {0, 0, 0, 0, 0, 0, 0, 0};
        for (int jj = g; jj < cnt; jj += 8) {
            int j = s_nbr[jj];
            uint4 v = g_h1b[(size_t)j * (C1 / 8) + c8];
            float w = wrow[jj];
            acc[0] += w * bflo(v.x); acc[1] += w * bfhi(v.x);
            acc[2] += w * bflo(v.y); acc[3] += w * bfhi(v.y);
            acc[4] += w * bflo(v.z); acc[5] += w * bfhi(v.z);
            acc[6] += w * bflo(v.w); acc[7] += w * bfhi(v.w);
        }
        #pragma unroll
        for (int k = 0; k < 8; k++) s_red[g][k][c8] = acc[k];
        __syncthreads();

        if (t < 64) {
            float inv = 1.0f / s_den[t >> 3];
            float o[8];
            #pragma unroll
            for (int k = 0; k < 8; k++) {
                float s = 0.0f;
                #pragma unroll
                for (int gg = 0; gg < 8; gg++) s += s_red[gg][k][t];
                float v = s * inv + b1[t * 8 + k];
                o[k] = v > 0.0f ? v : 0.01f * v;
            }
            float4* dst = (float4*)&g_hmid[(size_t)i * C1 + t * 8];
            dst[0] = make_float4(o[0], o[1], o[2], o[3]);
            dst[1] = make_float4(o[4], o[5], o[6], o[7]);
        }
    }
}

// ---------------- layer-2 sparse aggregation (256 thr, 16 groups) ----------------
__global__ void __launch_bounds__(256) agg2(const float* __restrict__ b2,
                                            float* __restrict__ out) {
    int i = blockIdx.x;
    int t = threadIdx.x;                  // 256
    __shared__ unsigned short s_nbr[MAXN];
    __shared__ float s_w[MAXN];
    __shared__ float s_part[256];
    __shared__ float s_den;
    __shared__ float s_red[16][8][16];    // 8KB

    int cnt = g_cnt[i];
    for (int jj = t; jj < cnt; jj += 256) s_nbr[jj] = g_nbr[(size_t)i * MAXN + jj];
    __syncthreads();

    float adst = g_adst2[i];
    for (int jj = t; jj < cnt; jj += 256) {
        float v = g_asrc2[s_nbr[jj]] + adst;
        v = v > 0.0f ? v : 0.2f * v;
        s_w[jj] = __expf(v);
    }
    __syncthreads();

    float s = 0.0f;
    for (int jj = t; jj < cnt; jj += 256) s += s_w[jj];
    s_part[t] = s;
    __syncthreads();
    for (int off = 128; off >= 1; off >>= 1) {
        if (t < off) s_part[t] += s_part[t + off];
        __syncthreads();
    }
    if (t == 0) s_den = s_part[0];
    __syncthreads();

    {
        int c8 = t & 15;
        int g  = t >> 4;                  // 0..15
        float acc[8] = {0, 0, 0, 0, 0, 0, 0, 0};
        for (int jj = g; jj < cnt; jj += 16) {
            int j = s_nbr[jj];
            uint4 v = g_h2b[(size_t)j * (OUT2 / 8) + c8];
            float w = s_w[jj];
            acc[0] += w * bflo(v.x); acc[1] += w * bfhi(v.x);
            acc[2] += w * bflo(v.y); acc[3] += w * bfhi(v.y);
            acc[4] += w * bflo(v.z); acc[5] += w * bfhi(v.z);
            acc[6] += w * bflo(v.w); acc[7] += w * bfhi(v.w);
        }
        #pragma unroll
        for (int k = 0; k < 8; k++) s_red[g][k][c8] = acc[k];
        __syncthreads();

        if (t < 16) {
            float inv = 1.0f / s_den;
            float o[8];
            #pragma unroll
            for (int k = 0; k < 8; k++) {
                float ss = 0.0f;
                #pragma unroll
                for (int gg = 0; gg < 16; gg++) ss += s_red[gg][k][t];
                float v = ss * inv + b2[t * 8 + k];
                o[k] = v > 0.0f ? v : 0.01f * v;
            }
            float4* dst = (float4*)&out[(size_t)i * OUT2 + t * 8];
            dst[0] = make_float4(o[0], o[1], o[2], o[3]);
            dst[1] = make_float4(o[4], o[5], o[6], o[7]);
        }
    }
}

// ---------------- launch ----------------
extern "C" void kernel_launch(void* const* d_in, const int* in_sizes, int n_in,
                              void* d_out, int out_size) {
    const float* x   = (const float*)d_in[0];
    const float* adj = (const float*)d_in[1];
    const float* w1  = (const float*)d_in[2];
    const float* as1 = (const float*)d_in[3];
    const float* ad1 = (const float*)d_in[4];
    const float* b1  = (const float*)d_in[5];
    const float* w2  = (const float*)d_in[6];
    const float* as2 = (const float*)d_in[7];
    const float* ad2 = (const float*)d_in[8];
    const float* b2  = (const float*)d_in[9];
    float* out = (float*)d_out;

    float *h1p, *hmidp, *h2p, *asrc1p, *adst1p, *p2sp, *p2dp;
    __nv_bfloat162 *h1bp, *h2bp;
    cudaGetSymbolAddress((void**)&h1p,    g_h1);
    cudaGetSymbolAddress((void**)&hmidp,  g_hmid);
    cudaGetSymbolAddress((void**)&h2p,    g_h2);
    cudaGetSymbolAddress((void**)&h1bp,   g_h1b);
    cudaGetSymbolAddress((void**)&h2bp,   g_h2b);
    cudaGetSymbolAddress((void**)&asrc1p, g_asrc1);
    cudaGetSymbolAddress((void**)&adst1p, g_adst1);
    cudaGetSymbolAddress((void**)&p2sp,   g_p2s);
    cudaGetSymbolAddress((void**)&p2dp,   g_p2d);

    build_csr<<<NN, 256>>>(adj);

    // h1 = x @ w1 (tf32 MMA, + bf16 copy, + fused scores1)
    // BM=64: grid = 4 x 64 = 256 CTAs (was 128)
    gemm_tf32<64, 128, 32, 32, 2, 4, 2, true><<<dim3(C1 / 128, NN / 64), 256>>>(
        x, w1, h1p, h1bp, as1, ad1, asrc1p, adst1p, NN, C1, FIN);

    agg1<<<NN, C1>>>(b1);

    // h2 = hmid @ w2 (tf32 MMA, + bf16 copy, + fused score partials)
    // BM=32: grid = 2 x 128 = 256 CTAs (was 128)
    gemm_tf32<32, 64, 16, 16, 1, 2, 1, false><<<dim3(OUT2 / 64, NN / 32), 256>>>(
        hmidp, w2, h2p, h2bp, as2, ad2, p2sp, p2dp, NN, OUT2, C1);

    reduce2<<<NN / 256, 256>>>();

    agg2<<<NN, 256>>>(b2, out);
}